// round 3
// baseline (speedup 1.0000x reference)
#include <cuda_runtime.h>

typedef unsigned long long ull;

#define MAXN 50000

// ---------------- device scratch (no allocations allowed) ----------------
__device__ float g_S   [MAXN * 64];
__device__ float g_deg [MAXN];
__device__ float g_h1  [MAXN * 32];
__device__ float g_h2  [MAXN * 32];
__device__ float g_En  [MAXN * 64];
__device__ float g_Enew[MAXN * 64];

// ---------------- helpers ----------------
__device__ __forceinline__ void fma4(float4& acc, float s, const float4& wv) {
    acc.x += s * wv.x; acc.y += s * wv.y; acc.z += s * wv.z; acc.w += s * wv.w;
}

__device__ __forceinline__ ull pack2(float a, float b) {
    ull r; asm("mov.b64 %0, {%1, %2};" : "=l"(r) : "f"(a), "f"(b)); return r;
}
__device__ __forceinline__ void unpack2(ull v, float& a, float& b) {
    asm("mov.b64 {%0, %1}, %2;" : "=f"(a), "=f"(b) : "l"(v));
}
__device__ __forceinline__ ull ffma2(ull a, ull b, ull c) {
    ull d; asm("fma.rn.f32x2 %0, %1, %2, %3;" : "=l"(d) : "l"(a), "l"(b), "l"(c));
    return d;
}
__device__ __forceinline__ float tanh_fast(float x) {
    float y; asm("tanh.approx.f32 %0, %1;" : "=f"(y) : "f"(x)); return y;
}

// ---------------- kernel 1: per-node h1/h2 = q @ WencP{1,2} + b ----------
__global__ __launch_bounds__(128) void node_pre(
    const float* __restrict__ x,
    const float* __restrict__ W1, const float* __restrict__ b1,
    const float* __restrict__ W2, const float* __restrict__ b2, int n)
{
    __shared__ float4 sW1[32 * 8], sW2[32 * 8], sb1[8], sb2[8];
    for (int i = threadIdx.x; i < 32 * 8; i += 128) {
        sW1[i] = ((const float4*)W1)[i];
        sW2[i] = ((const float4*)W2)[i];
    }
    if (threadIdx.x < 8) {
        sb1[threadIdx.x] = ((const float4*)b1)[threadIdx.x];
        sb2[threadIdx.x] = ((const float4*)b2)[threadIdx.x];
    }
    __syncthreads();
    int i = blockIdx.x * 128 + threadIdx.x;
    if (i >= n) return;

    float q[32];
    const float4* xp = (const float4*)(x + (size_t)i * 64);
#pragma unroll
    for (int k4 = 0; k4 < 8; k4++) {
        float4 v = xp[k4];
        q[4*k4] = v.x; q[4*k4+1] = v.y; q[4*k4+2] = v.z; q[4*k4+3] = v.w;
    }
    float4* o1 = (float4*)(g_h1 + (size_t)i * 32);
    float4* o2 = (float4*)(g_h2 + (size_t)i * 32);
#pragma unroll
    for (int jb = 0; jb < 8; jb++) {
        float4 a1 = sb1[jb], a2 = sb2[jb];
#pragma unroll
        for (int k = 0; k < 32; k++) {
            fma4(a1, q[k], sW1[k*8 + jb]);
            fma4(a2, q[k], sW2[k*8 + jb]);
        }
        o1[jb] = a1;
        o2[jb] = a2;
    }
}

// ---------------- kernel 2: S = segment_sum(x[src], dst), deg ------------
__global__ void edge_scatter(const float* __restrict__ x,
                             const int* __restrict__ src,
                             const int* __restrict__ dst, int e_total)
{
    int t = blockIdx.x * blockDim.x + threadIdx.x;
    int e = t >> 4;
    if (e >= e_total) return;
    int j4 = t & 15;
    int s = __ldg(src + e);
    int d = __ldg(dst + e);
    float4 v = __ldg((const float4*)(x + (size_t)s * 64) + j4);
    float* o = g_S + (size_t)d * 64 + j4 * 4;
    atomicAdd(o + 0, v.x);
    atomicAdd(o + 1, v.y);
    atomicAdd(o + 2, v.z);
    atomicAdd(o + 3, v.w);
    if (j4 == 0) atomicAdd(&g_deg[d], 1.0f);
}

// ------ kernel 3: hK_agg = S[:,32:]@WencK + deg*b ; E_node = mlp3 --------
__global__ __launch_bounds__(128) void node_mid(
    const float* __restrict__ WencK, const float* __restrict__ bencK,
    const float* __restrict__ WK1, const float* __restrict__ bK1,
    const float* __restrict__ WK2, const float* __restrict__ bK2,
    const float* __restrict__ WK3, const float* __restrict__ bK3, int n)
{
    __shared__ float4 sWe[32 * 8],  sbe[8];
    __shared__ float4 sW1[32 * 16], sb1[16];
    __shared__ float4 sW2[64 * 16], sb2[16];
    __shared__ float4 sW3[64 * 16], sb3[16];
    for (int i = threadIdx.x; i < 32 * 8;  i += 128) sWe[i] = ((const float4*)WencK)[i];
    for (int i = threadIdx.x; i < 32 * 16; i += 128) sW1[i] = ((const float4*)WK1)[i];
    for (int i = threadIdx.x; i < 64 * 16; i += 128) sW2[i] = ((const float4*)WK2)[i];
    for (int i = threadIdx.x; i < 64 * 16; i += 128) sW3[i] = ((const float4*)WK3)[i];
    if (threadIdx.x < 8)  sbe[threadIdx.x] = ((const float4*)bencK)[threadIdx.x];
    if (threadIdx.x < 16) {
        sb1[threadIdx.x] = ((const float4*)bK1)[threadIdx.x];
        sb2[threadIdx.x] = ((const float4*)bK2)[threadIdx.x];
        sb3[threadIdx.x] = ((const float4*)bK3)[threadIdx.x];
    }
    __syncthreads();
    int i = blockIdx.x * 128 + threadIdx.x;
    if (i >= n) return;

    float p[32];
    const float4* Sp = (const float4*)(g_S + (size_t)i * 64);
#pragma unroll
    for (int k4 = 0; k4 < 8; k4++) {
        float4 v = Sp[8 + k4];
        p[4*k4] = v.x; p[4*k4+1] = v.y; p[4*k4+2] = v.z; p[4*k4+3] = v.w;
    }
    float dg = g_deg[i];

    float hK[32];
#pragma unroll
    for (int jb = 0; jb < 8; jb++) {
        float4 b = sbe[jb];
        float4 acc = make_float4(dg*b.x, dg*b.y, dg*b.z, dg*b.w);
#pragma unroll
        for (int k = 0; k < 32; k++) fma4(acc, p[k], sWe[k*8 + jb]);
        hK[4*jb] = acc.x; hK[4*jb+1] = acc.y; hK[4*jb+2] = acc.z; hK[4*jb+3] = acc.w;
    }

    float t1[64];
#pragma unroll
    for (int jb = 0; jb < 16; jb++) {
        float4 acc = sb1[jb];
#pragma unroll
        for (int k = 0; k < 32; k++) fma4(acc, hK[k], sW1[k*16 + jb]);
        t1[4*jb]   = tanh_fast(acc.x); t1[4*jb+1] = tanh_fast(acc.y);
        t1[4*jb+2] = tanh_fast(acc.z); t1[4*jb+3] = tanh_fast(acc.w);
    }

    float t2[64];
#pragma unroll
    for (int jb = 0; jb < 16; jb++) {
        float4 acc = sb2[jb];
#pragma unroll
        for (int k = 0; k < 64; k++) fma4(acc, t1[k], sW2[k*16 + jb]);
        t2[4*jb]   = fmaxf(acc.x, 0.f); t2[4*jb+1] = fmaxf(acc.y, 0.f);
        t2[4*jb+2] = fmaxf(acc.z, 0.f); t2[4*jb+3] = fmaxf(acc.w, 0.f);
    }

    float4* Eo = (float4*)(g_En + (size_t)i * 64);
#pragma unroll
    for (int jb = 0; jb < 16; jb++) {
        float4 acc = sb3[jb];
#pragma unroll
        for (int k = 0; k < 64; k++) fma4(acc, t2[k], sW3[k*16 + jb]);
        Eo[jb] = acc;
    }
}

// ------ kernel 4 (dominant): per-edge MLP + scatter into E_new -----------
// f32x2 packed math; weights in smem as ulonglong2 (raw fp32 pairs).
__global__ void __launch_bounds__(128, 4) edge_mlp(
    const int* __restrict__ src, const int* __restrict__ dst,
    const float* __restrict__ WU1, const float* __restrict__ bU1,
    const float* __restrict__ WU2, const float* __restrict__ bU2,
    const float* __restrict__ WU3, const float* __restrict__ bU3, int e_total)
{
    // W1: [32][64] -> 32*16 ull2 ; W2/W3: [64][64] -> 64*16 ull2
    __shared__ ulonglong2 sW1[32 * 16], sW2[64 * 16], sW3[64 * 16];
    __shared__ ull sb1[32], sb2[32], sb3[32];
    for (int i = threadIdx.x; i < 32 * 16; i += 128) sW1[i] = ((const ulonglong2*)WU1)[i];
    for (int i = threadIdx.x; i < 64 * 16; i += 128) sW2[i] = ((const ulonglong2*)WU2)[i];
    for (int i = threadIdx.x; i < 64 * 16; i += 128) sW3[i] = ((const ulonglong2*)WU3)[i];
    if (threadIdx.x < 32) {
        sb1[threadIdx.x] = ((const ull*)bU1)[threadIdx.x];
        sb2[threadIdx.x] = ((const ull*)bU2)[threadIdx.x];
        sb3[threadIdx.x] = ((const ull*)bU3)[threadIdx.x];
    }
    __syncthreads();

    for (int e = blockIdx.x * blockDim.x + threadIdx.x; e < e_total;
         e += gridDim.x * blockDim.x) {
        int s = __ldg(src + e);
        int d = __ldg(dst + e);

        // ---- gather eo = h1[s] + h2[d] ----
        float eo[32];
        const float4* h1p = (const float4*)(g_h1 + (size_t)s * 32);
        const float4* h2p = (const float4*)(g_h2 + (size_t)d * 32);
#pragma unroll
        for (int k4 = 0; k4 < 8; k4++) {
            float4 a = __ldg(h1p + k4), b = __ldg(h2p + k4);
            eo[4*k4]   = a.x + b.x; eo[4*k4+1] = a.y + b.y;
            eo[4*k4+2] = a.z + b.z; eo[4*k4+3] = a.w + b.w;
        }

        // ---- layer 1: [32] -> [64], tanh ----
        float h[64];
        {
            ull acc[32];
#pragma unroll
            for (int j = 0; j < 32; j++) acc[j] = sb1[j];
#pragma unroll
            for (int k = 0; k < 32; k++) {
                ull s2 = pack2(eo[k], eo[k]);
#pragma unroll
                for (int jq = 0; jq < 16; jq++) {
                    ulonglong2 w = sW1[k*16 + jq];
                    acc[2*jq]   = ffma2(s2, w.x, acc[2*jq]);
                    acc[2*jq+1] = ffma2(s2, w.y, acc[2*jq+1]);
                }
            }
#pragma unroll
            for (int j = 0; j < 32; j++) {
                float a, b; unpack2(acc[j], a, b);
                h[2*j]   = tanh_fast(a);
                h[2*j+1] = tanh_fast(b);
            }
        }

        // ---- layer 2: [64] -> [64], relu (two output halves) ----
        float hh[64];
#pragma unroll
        for (int half = 0; half < 2; half++) {
            ull acc[16];
#pragma unroll
            for (int j = 0; j < 16; j++) acc[j] = sb2[half*16 + j];
#pragma unroll
            for (int k = 0; k < 64; k++) {
                ull s2 = pack2(h[k], h[k]);
#pragma unroll
                for (int jq = 0; jq < 8; jq++) {
                    ulonglong2 w = sW2[k*16 + half*8 + jq];
                    acc[2*jq]   = ffma2(s2, w.x, acc[2*jq]);
                    acc[2*jq+1] = ffma2(s2, w.y, acc[2*jq+1]);
                }
            }
#pragma unroll
            for (int j = 0; j < 16; j++) {
                float a, b; unpack2(acc[j], a, b);
                hh[half*32 + 2*j]   = fmaxf(a, 0.f);
                hh[half*32 + 2*j+1] = fmaxf(b, 0.f);
            }
        }

        // ---- layer 3: [64] -> [64], * E_node[s], scatter-add to dst ----
        const float* Enp = g_En + (size_t)s * 64;
        float* Ew = g_Enew + (size_t)d * 64;
#pragma unroll
        for (int half = 0; half < 2; half++) {
            ull acc[16];
#pragma unroll
            for (int j = 0; j < 16; j++) acc[j] = sb3[half*16 + j];
#pragma unroll
            for (int k = 0; k < 64; k++) {
                ull s2 = pack2(hh[k], hh[k]);
#pragma unroll
                for (int jq = 0; jq < 8; jq++) {
                    ulonglong2 w = sW3[k*16 + half*8 + jq];
                    acc[2*jq]   = ffma2(s2, w.x, acc[2*jq]);
                    acc[2*jq+1] = ffma2(s2, w.y, acc[2*jq+1]);
                }
            }
#pragma unroll
            for (int j = 0; j < 16; j++) {
                float a, b; unpack2(acc[j], a, b);
                int col = half*32 + 2*j;
                float e0 = __ldg(Enp + col);
                float e1 = __ldg(Enp + col + 1);
                atomicAdd(Ew + col,     a * e0);
                atomicAdd(Ew + col + 1, b * e1);
            }
        }
    }
}

// ------ kernel 5: dH = E_new@WH + bH ; d_agg = S@WD[:,32:] + deg*b ; out -
__global__ __launch_bounds__(128) void node_post(
    const float* __restrict__ WH, const float* __restrict__ bH,
    const float* __restrict__ WD, const float* __restrict__ bD,
    float* __restrict__ out, int n)
{
    __shared__ float4 sWH[64 * 16], sbH[16];
    __shared__ float4 sWD[64 * 8],  sbD[8];
    for (int i = threadIdx.x; i < 64 * 16; i += 128) sWH[i] = ((const float4*)WH)[i];
    for (int i = threadIdx.x; i < 64 * 8; i += 128) {
        int k = i >> 3, jb = i & 7;
        sWD[i] = ((const float4*)(WD + k * 64 + 32))[jb];
    }
    if (threadIdx.x < 16) sbH[threadIdx.x] = ((const float4*)bH)[threadIdx.x];
    if (threadIdx.x < 8)  sbD[threadIdx.x] = ((const float4*)(bD + 32))[threadIdx.x];
    __syncthreads();
    int i = blockIdx.x * 128 + threadIdx.x;
    if (i >= n) return;

    float En[64];
    const float4* Ep = (const float4*)(g_Enew + (size_t)i * 64);
#pragma unroll
    for (int k4 = 0; k4 < 16; k4++) {
        float4 v = Ep[k4];
        En[4*k4] = v.x; En[4*k4+1] = v.y; En[4*k4+2] = v.z; En[4*k4+3] = v.w;
    }

    float4* op = (float4*)(out + (size_t)i * 64);
    float dlo[32];
#pragma unroll
    for (int jb = 0; jb < 16; jb++) {
        float4 acc = sbH[jb];
#pragma unroll
        for (int k = 0; k < 64; k++) fma4(acc, En[k], sWH[k*16 + jb]);
        if (jb >= 8) {
            op[jb - 8] = acc;
        } else {
            dlo[4*jb] = acc.x; dlo[4*jb+1] = acc.y;
            dlo[4*jb+2] = acc.z; dlo[4*jb+3] = acc.w;
        }
    }

    float S[64];
    const float4* Sp = (const float4*)(g_S + (size_t)i * 64);
#pragma unroll
    for (int k4 = 0; k4 < 16; k4++) {
        float4 v = Sp[k4];
        S[4*k4] = v.x; S[4*k4+1] = v.y; S[4*k4+2] = v.z; S[4*k4+3] = v.w;
    }
    float dg = g_deg[i];
#pragma unroll
    for (int jb = 0; jb < 8; jb++) {
        float4 b = sbD[jb];
        float4 acc = make_float4(dg*b.x, dg*b.y, dg*b.z, dg*b.w);
#pragma unroll
        for (int k = 0; k < 64; k++) fma4(acc, S[k], sWD[k*8 + jb]);
        float4 o;
        o.x = -dlo[4*jb]   - acc.x;
        o.y = -dlo[4*jb+1] - acc.y;
        o.z = -dlo[4*jb+2] - acc.z;
        o.w = -dlo[4*jb+3] - acc.w;
        op[8 + jb] = o;
    }
}

// -------------------------------------------------------------------------
extern "C" void kernel_launch(void* const* d_in, const int* in_sizes, int n_in,
                              void* d_out, int out_size)
{
    const float* x      = (const float*)d_in[0];
    const int*   src    = (const int*)  d_in[1];
    const int*   dst    = (const int*)  d_in[2];
    const float* WencK  = (const float*)d_in[3];
    const float* bencK  = (const float*)d_in[4];
    const float* WencP1 = (const float*)d_in[5];
    const float* bencP1 = (const float*)d_in[6];
    const float* WencP2 = (const float*)d_in[7];
    const float* bencP2 = (const float*)d_in[8];
    const float* WK1 = (const float*)d_in[9];
    const float* bK1 = (const float*)d_in[10];
    const float* WK2 = (const float*)d_in[11];
    const float* bK2 = (const float*)d_in[12];
    const float* WK3 = (const float*)d_in[13];
    const float* bK3 = (const float*)d_in[14];
    const float* WU1 = (const float*)d_in[15];
    const float* bU1 = (const float*)d_in[16];
    const float* WU2 = (const float*)d_in[17];
    const float* bU2 = (const float*)d_in[18];
    const float* WU3 = (const float*)d_in[19];
    const float* bU3 = (const float*)d_in[20];
    const float* WH  = (const float*)d_in[21];
    const float* bH  = (const float*)d_in[22];
    const float* WD  = (const float*)d_in[23];
    const float* bD  = (const float*)d_in[24];

    int n = in_sizes[0] / 64;
    int e = in_sizes[1];
    if (n > MAXN) n = MAXN;

    void *pS, *pdeg, *pEnew;
    cudaGetSymbolAddress(&pS,    g_S);
    cudaGetSymbolAddress(&pdeg,  g_deg);
    cudaGetSymbolAddress(&pEnew, g_Enew);
    cudaMemsetAsync(pS,    0, (size_t)n * 64 * sizeof(float));
    cudaMemsetAsync(pdeg,  0, (size_t)n * sizeof(float));
    cudaMemsetAsync(pEnew, 0, (size_t)n * 64 * sizeof(float));

    int nb = (n + 127) / 128;
    node_pre<<<nb, 128>>>(x, WencP1, bencP1, WencP2, bencP2, n);
    edge_scatter<<<((size_t)e * 16 + 255) / 256, 256>>>(x, src, dst, e);
    node_mid<<<nb, 128>>>(WencK, bencK, WK1, bK1, WK2, bK2, WK3, bK3, n);
    edge_mlp<<<592, 128>>>(src, dst, WU1, bU1, WU2, bU2, WU3, bU3, e);
    node_post<<<nb, 128>>>(WH, bH, WD, bD, (float*)d_out, n);
}

// round 5
// speedup vs baseline: 1.8955x; 1.8955x over previous
#include <cuda_runtime.h>

typedef unsigned long long ull;

#define MAXN 50000

// ---------------- device scratch (no allocations allowed) ----------------
__device__ float g_S   [MAXN * 64];
__device__ float g_deg [MAXN];
__device__ float g_h1  [MAXN * 32];
__device__ float g_h2  [MAXN * 32];
__device__ float g_En  [MAXN * 64];
__device__ float g_Enew[MAXN * 64];

// ---------------- helpers ----------------
__device__ __forceinline__ void fma4(float4& acc, float s, const float4& wv) {
    acc.x += s * wv.x; acc.y += s * wv.y; acc.z += s * wv.z; acc.w += s * wv.w;
}
__device__ __forceinline__ ull pack2(float a, float b) {
    ull r; asm("mov.b64 %0, {%1, %2};" : "=l"(r) : "f"(a), "f"(b)); return r;
}
__device__ __forceinline__ void unpack2(ull v, float& a, float& b) {
    asm("mov.b64 {%0, %1}, %2;" : "=f"(a), "=f"(b) : "l"(v));
}
__device__ __forceinline__ ull ffma2(ull a, ull b, ull c) {
    ull d; asm("fma.rn.f32x2 %0, %1, %2, %3;" : "=l"(d) : "l"(a), "l"(b), "l"(c));
    return d;
}
__device__ __forceinline__ float tanh_fast(float x) {
    float y; asm("tanh.approx.f32 %0, %1;" : "=f"(y) : "f"(x)); return y;
}

// ---------------- kernel 1: per-node h1/h2 = q @ WencP{1,2} + b ----------
__global__ __launch_bounds__(128) void node_pre(
    const float* __restrict__ x,
    const float* __restrict__ W1, const float* __restrict__ b1,
    const float* __restrict__ W2, const float* __restrict__ b2, int n)
{
    __shared__ float4 sW1[32 * 8], sW2[32 * 8], sb1[8], sb2[8];
    for (int i = threadIdx.x; i < 32 * 8; i += 128) {
        sW1[i] = ((const float4*)W1)[i];
        sW2[i] = ((const float4*)W2)[i];
    }
    if (threadIdx.x < 8) {
        sb1[threadIdx.x] = ((const float4*)b1)[threadIdx.x];
        sb2[threadIdx.x] = ((const float4*)b2)[threadIdx.x];
    }
    __syncthreads();
    int i = blockIdx.x * 128 + threadIdx.x;
    if (i >= n) return;

    float q[32];
    const float4* xp = (const float4*)(x + (size_t)i * 64);
#pragma unroll
    for (int k4 = 0; k4 < 8; k4++) {
        float4 v = xp[k4];
        q[4*k4] = v.x; q[4*k4+1] = v.y; q[4*k4+2] = v.z; q[4*k4+3] = v.w;
    }
    float4* o1 = (float4*)(g_h1 + (size_t)i * 32);
    float4* o2 = (float4*)(g_h2 + (size_t)i * 32);
#pragma unroll
    for (int jb = 0; jb < 8; jb++) {
        float4 a1 = sb1[jb], a2 = sb2[jb];
#pragma unroll
        for (int k = 0; k < 32; k++) {
            fma4(a1, q[k], sW1[k*8 + jb]);
            fma4(a2, q[k], sW2[k*8 + jb]);
        }
        o1[jb] = a1;
        o2[jb] = a2;
    }
}

// ---------------- kernel 2: S = segment_sum(x[src], dst), deg ------------
__global__ void edge_scatter(const float* __restrict__ x,
                             const int* __restrict__ src,
                             const int* __restrict__ dst, int e_total)
{
    int t = blockIdx.x * blockDim.x + threadIdx.x;
    int e = t >> 4;
    if (e >= e_total) return;
    int j4 = t & 15;
    int s = __ldg(src + e);
    int d = __ldg(dst + e);
    float4 v = __ldg((const float4*)(x + (size_t)s * 64) + j4);
    float* o = g_S + (size_t)d * 64 + j4 * 4;
    atomicAdd(o + 0, v.x);
    atomicAdd(o + 1, v.y);
    atomicAdd(o + 2, v.z);
    atomicAdd(o + 3, v.w);
    if (j4 == 0) atomicAdd(&g_deg[d], 1.0f);
}

// ------ kernel 3: hK_agg = S[:,32:]@WencK + deg*b ; E_node = mlp3 --------
__global__ __launch_bounds__(128) void node_mid(
    const float* __restrict__ WencK, const float* __restrict__ bencK,
    const float* __restrict__ WK1, const float* __restrict__ bK1,
    const float* __restrict__ WK2, const float* __restrict__ bK2,
    const float* __restrict__ WK3, const float* __restrict__ bK3, int n)
{
    __shared__ float4 sWe[32 * 8],  sbe[8];
    __shared__ float4 sW1[32 * 16], sb1[16];
    __shared__ float4 sW2[64 * 16], sb2[16];
    __shared__ float4 sW3[64 * 16], sb3[16];
    for (int i = threadIdx.x; i < 32 * 8;  i += 128) sWe[i] = ((const float4*)WencK)[i];
    for (int i = threadIdx.x; i < 32 * 16; i += 128) sW1[i] = ((const float4*)WK1)[i];
    for (int i = threadIdx.x; i < 64 * 16; i += 128) sW2[i] = ((const float4*)WK2)[i];
    for (int i = threadIdx.x; i < 64 * 16; i += 128) sW3[i] = ((const float4*)WK3)[i];
    if (threadIdx.x < 8)  sbe[threadIdx.x] = ((const float4*)bencK)[threadIdx.x];
    if (threadIdx.x < 16) {
        sb1[threadIdx.x] = ((const float4*)bK1)[threadIdx.x];
        sb2[threadIdx.x] = ((const float4*)bK2)[threadIdx.x];
        sb3[threadIdx.x] = ((const float4*)bK3)[threadIdx.x];
    }
    __syncthreads();
    int i = blockIdx.x * 128 + threadIdx.x;
    if (i >= n) return;

    float p[32];
    const float4* Sp = (const float4*)(g_S + (size_t)i * 64);
#pragma unroll
    for (int k4 = 0; k4 < 8; k4++) {
        float4 v = Sp[8 + k4];
        p[4*k4] = v.x; p[4*k4+1] = v.y; p[4*k4+2] = v.z; p[4*k4+3] = v.w;
    }
    float dg = g_deg[i];

    float hK[32];
#pragma unroll
    for (int jb = 0; jb < 8; jb++) {
        float4 b = sbe[jb];
        float4 acc = make_float4(dg*b.x, dg*b.y, dg*b.z, dg*b.w);
#pragma unroll
        for (int k = 0; k < 32; k++) fma4(acc, p[k], sWe[k*8 + jb]);
        hK[4*jb] = acc.x; hK[4*jb+1] = acc.y; hK[4*jb+2] = acc.z; hK[4*jb+3] = acc.w;
    }

    float t1[64];
#pragma unroll
    for (int jb = 0; jb < 16; jb++) {
        float4 acc = sb1[jb];
#pragma unroll
        for (int k = 0; k < 32; k++) fma4(acc, hK[k], sW1[k*16 + jb]);
        t1[4*jb]   = tanh_fast(acc.x); t1[4*jb+1] = tanh_fast(acc.y);
        t1[4*jb+2] = tanh_fast(acc.z); t1[4*jb+3] = tanh_fast(acc.w);
    }

    float t2[64];
#pragma unroll
    for (int jb = 0; jb < 16; jb++) {
        float4 acc = sb2[jb];
#pragma unroll
        for (int k = 0; k < 64; k++) fma4(acc, t1[k], sW2[k*16 + jb]);
        t2[4*jb]   = fmaxf(acc.x, 0.f); t2[4*jb+1] = fmaxf(acc.y, 0.f);
        t2[4*jb+2] = fmaxf(acc.z, 0.f); t2[4*jb+3] = fmaxf(acc.w, 0.f);
    }

    float4* Eo = (float4*)(g_En + (size_t)i * 64);
#pragma unroll
    for (int jb = 0; jb < 16; jb++) {
        float4 acc = sb3[jb];
#pragma unroll
        for (int k = 0; k < 64; k++) fma4(acc, t2[k], sW3[k*16 + jb]);
        Eo[jb] = acc;
    }
}

// ======================= kernel 4: tiled edge MLP =========================
// Block = 128 threads, tile = 64 edges. Thread grid 8 (edge groups) x 16 (col
// groups); each thread owns 8 edges x 4 cols = 16 f32x2 accumulators.
// Activations in smem transposed + pair-duplicated: A[k][2e] = A[k][2e+1] =
// act(edge e, feature k), so the edge-pair FFMA2 operand is a direct LDS.128.
// ROWW must keep every row 16B-aligned: ROWW*4 % 16 == 0 -> ROWW = 132.
static constexpr int ROWW = 132;          // floats per A row (128 dup + 4 pad)
static constexpr int EDGE_SMEM = 42240 + 64 * ROWW * 4;   // 76032 bytes

template<int K>
__device__ __forceinline__ void gemm_f32x2(ull acc[16], const float* sA,
                                           const ulonglong2* sW, const ull* sb,
                                           int tr, int tc)
{
#pragma unroll
    for (int e = 0; e < 8; e++) { acc[2*e] = sb[2*tc]; acc[2*e+1] = sb[2*tc+1]; }
#pragma unroll 8
    for (int k = 0; k < K; k++) {
        const ulonglong2* ap = (const ulonglong2*)&sA[k*ROWW + 16*tr];
        ulonglong2 A0 = ap[0], A1 = ap[1], A2 = ap[2], A3 = ap[3];
        ulonglong2 B  = sW[k*16 + tc];
        acc[0]  = ffma2(A0.x, B.x, acc[0]);  acc[1]  = ffma2(A0.x, B.y, acc[1]);
        acc[2]  = ffma2(A0.y, B.x, acc[2]);  acc[3]  = ffma2(A0.y, B.y, acc[3]);
        acc[4]  = ffma2(A1.x, B.x, acc[4]);  acc[5]  = ffma2(A1.x, B.y, acc[5]);
        acc[6]  = ffma2(A1.y, B.x, acc[6]);  acc[7]  = ffma2(A1.y, B.y, acc[7]);
        acc[8]  = ffma2(A2.x, B.x, acc[8]);  acc[9]  = ffma2(A2.x, B.y, acc[9]);
        acc[10] = ffma2(A2.y, B.x, acc[10]); acc[11] = ffma2(A2.y, B.y, acc[11]);
        acc[12] = ffma2(A3.x, B.x, acc[12]); acc[13] = ffma2(A3.x, B.y, acc[13]);
        acc[14] = ffma2(A3.y, B.x, acc[14]); acc[15] = ffma2(A3.y, B.y, acc[15]);
    }
}

__global__ __launch_bounds__(128) void edge_mlp(
    const int* __restrict__ src, const int* __restrict__ dst,
    const float* __restrict__ WU1, const float* __restrict__ bU1,
    const float* __restrict__ WU2, const float* __restrict__ bU2,
    const float* __restrict__ WU3, const float* __restrict__ bU3, int e_total)
{
    extern __shared__ char smem[];
    ulonglong2* sW1 = (ulonglong2*)(smem + 0);      // 32x16  (8 KB)
    ulonglong2* sW2 = (ulonglong2*)(smem + 8192);   // 64x16  (16 KB)
    ulonglong2* sW3 = (ulonglong2*)(smem + 24576);  // 64x16  (16 KB)
    ull* sb1 = (ull*)(smem + 40960);
    ull* sb2 = (ull*)(smem + 41216);
    ull* sb3 = (ull*)(smem + 41472);
    int* sSrc = (int*)(smem + 41728);
    int* sDst = (int*)(smem + 41984);
    float* sA = (float*)(smem + 42240);             // 64 x 132 floats

    int tid = threadIdx.x;
    for (int i = tid; i < 512;  i += 128) sW1[i] = ((const ulonglong2*)WU1)[i];
    for (int i = tid; i < 1024; i += 128) sW2[i] = ((const ulonglong2*)WU2)[i];
    for (int i = tid; i < 1024; i += 128) sW3[i] = ((const ulonglong2*)WU3)[i];
    if (tid < 32) {
        sb1[tid] = ((const ull*)bU1)[tid];
        sb2[tid] = ((const ull*)bU2)[tid];
        sb3[tid] = ((const ull*)bU3)[tid];
    }
    __syncthreads();

    int tr = tid >> 4;      // 0..7  -> edges tr*8 .. tr*8+7
    int tc = tid & 15;      // 0..15 -> cols  tc*4 .. tc*4+3
    int e0 = tr * 8;
    int eh = tid & 63;      // gather: edge within tile
    int half = tid >> 6;    // gather: which 16 features

    int ntiles = (e_total + 63) >> 6;
    for (int t = blockIdx.x; t < ntiles; t += gridDim.x) {
        int base = t << 6;

        // ---- gather: eo = h1[src] + h2[dst], store dup-transposed ----
        {
            int ge = base + eh;
            bool valid = ge < e_total;
            int s = 0, d = 0;
            if (valid) { s = __ldg(src + ge); d = __ldg(dst + ge); }
            if (half == 0) { sSrc[eh] = s; sDst[eh] = d; }
            const float4* h1p = (const float4*)(g_h1 + (size_t)s * 32) + half * 4;
            const float4* h2p = (const float4*)(g_h2 + (size_t)d * 32) + half * 4;
#pragma unroll
            for (int q = 0; q < 4; q++) {
                float4 a = __ldg(h1p + q), b = __ldg(h2p + q);
                float v0 = valid ? a.x + b.x : 0.f;
                float v1 = valid ? a.y + b.y : 0.f;
                float v2 = valid ? a.z + b.z : 0.f;
                float v3 = valid ? a.w + b.w : 0.f;
                int kb = half * 16 + q * 4;
                *(ull*)&sA[(kb+0)*ROWW + 2*eh] = pack2(v0, v0);
                *(ull*)&sA[(kb+1)*ROWW + 2*eh] = pack2(v1, v1);
                *(ull*)&sA[(kb+2)*ROWW + 2*eh] = pack2(v2, v2);
                *(ull*)&sA[(kb+3)*ROWW + 2*eh] = pack2(v3, v3);
            }
        }
        __syncthreads();

        ull acc[16];

        // ---- layer 1: [32]->[64], tanh ----
        gemm_f32x2<32>(acc, sA, sW1, sb1, tr, tc);
        __syncthreads();
#pragma unroll
        for (int e = 0; e < 8; e++) {
#pragma unroll
            for (int cp = 0; cp < 2; cp++) {
                float a, b; unpack2(acc[2*e+cp], a, b);
                int c = 4*tc + 2*cp;
                float ta = tanh_fast(a), tb = tanh_fast(b);
                *(ull*)&sA[c*ROWW + 2*(e0+e)]     = pack2(ta, ta);
                *(ull*)&sA[(c+1)*ROWW + 2*(e0+e)] = pack2(tb, tb);
            }
        }
        __syncthreads();

        // ---- layer 2: [64]->[64], relu ----
        gemm_f32x2<64>(acc, sA, sW2, sb2, tr, tc);
        __syncthreads();
#pragma unroll
        for (int e = 0; e < 8; e++) {
#pragma unroll
            for (int cp = 0; cp < 2; cp++) {
                float a, b; unpack2(acc[2*e+cp], a, b);
                int c = 4*tc + 2*cp;
                float ra = fmaxf(a, 0.f), rb = fmaxf(b, 0.f);
                *(ull*)&sA[c*ROWW + 2*(e0+e)]     = pack2(ra, ra);
                *(ull*)&sA[(c+1)*ROWW + 2*(e0+e)] = pack2(rb, rb);
            }
        }
        __syncthreads();

        // ---- layer 3: [64]->[64], * E_node[src], scatter to E_new[dst] ----
        gemm_f32x2<64>(acc, sA, sW3, sb3, tr, tc);
#pragma unroll
        for (int e = 0; e < 8; e++) {
            int ee = e0 + e;
            if (base + ee < e_total) {
                int s = sSrc[ee], d = sDst[ee];
                float4 En4 = __ldg((const float4*)(g_En + (size_t)s * 64) + tc);
                float* Ew = g_Enew + (size_t)d * 64 + 4*tc;
                float a, b;
                unpack2(acc[2*e], a, b);
                atomicAdd(Ew + 0, a * En4.x);
                atomicAdd(Ew + 1, b * En4.y);
                unpack2(acc[2*e+1], a, b);
                atomicAdd(Ew + 2, a * En4.z);
                atomicAdd(Ew + 3, b * En4.w);
            }
        }
        __syncthreads();   // protect sA/sSrc before next tile's gather
    }
}

// ------ kernel 5: dH = E_new@WH + bH ; d_agg = S@WD[:,32:] + deg*b ; out -
__global__ __launch_bounds__(128) void node_post(
    const float* __restrict__ WH, const float* __restrict__ bH,
    const float* __restrict__ WD, const float* __restrict__ bD,
    float* __restrict__ out, int n)
{
    __shared__ float4 sWH[64 * 16], sbH[16];
    __shared__ float4 sWD[64 * 8],  sbD[8];
    for (int i = threadIdx.x; i < 64 * 16; i += 128) sWH[i] = ((const float4*)WH)[i];
    for (int i = threadIdx.x; i < 64 * 8; i += 128) {
        int k = i >> 3, jb = i & 7;
        sWD[i] = ((const float4*)(WD + k * 64 + 32))[jb];
    }
    if (threadIdx.x < 16) sbH[threadIdx.x] = ((const float4*)bH)[threadIdx.x];
    if (threadIdx.x < 8)  sbD[threadIdx.x] = ((const float4*)(bD + 32))[threadIdx.x];
    __syncthreads();
    int i = blockIdx.x * 128 + threadIdx.x;
    if (i >= n) return;

    float En[64];
    const float4* Ep = (const float4*)(g_Enew + (size_t)i * 64);
#pragma unroll
    for (int k4 = 0; k4 < 16; k4++) {
        float4 v = Ep[k4];
        En[4*k4] = v.x; En[4*k4+1] = v.y; En[4*k4+2] = v.z; En[4*k4+3] = v.w;
    }

    float4* op = (float4*)(out + (size_t)i * 64);
    float dlo[32];
#pragma unroll
    for (int jb = 0; jb < 16; jb++) {
        float4 acc = sbH[jb];
#pragma unroll
        for (int k = 0; k < 64; k++) fma4(acc, En[k], sWH[k*16 + jb]);
        if (jb >= 8) {
            op[jb - 8] = acc;
        } else {
            dlo[4*jb] = acc.x; dlo[4*jb+1] = acc.y;
            dlo[4*jb+2] = acc.z; dlo[4*jb+3] = acc.w;
        }
    }

    float S[64];
    const float4* Sp = (const float4*)(g_S + (size_t)i * 64);
#pragma unroll
    for (int k4 = 0; k4 < 16; k4++) {
        float4 v = Sp[k4];
        S[4*k4] = v.x; S[4*k4+1] = v.y; S[4*k4+2] = v.z; S[4*k4+3] = v.w;
    }
    float dg = g_deg[i];
#pragma unroll
    for (int jb = 0; jb < 8; jb++) {
        float4 b = sbD[jb];
        float4 acc = make_float4(dg*b.x, dg*b.y, dg*b.z, dg*b.w);
#pragma unroll
        for (int k = 0; k < 64; k++) fma4(acc, S[k], sWD[k*8 + jb]);
        float4 o;
        o.x = -dlo[4*jb]   - acc.x;
        o.y = -dlo[4*jb+1] - acc.y;
        o.z = -dlo[4*jb+2] - acc.z;
        o.w = -dlo[4*jb+3] - acc.w;
        op[8 + jb] = o;
    }
}

// -------------------------------------------------------------------------
extern "C" void kernel_launch(void* const* d_in, const int* in_sizes, int n_in,
                              void* d_out, int out_size)
{
    const float* x      = (const float*)d_in[0];
    const int*   src    = (const int*)  d_in[1];
    const int*   dst    = (const int*)  d_in[2];
    const float* WencK  = (const float*)d_in[3];
    const float* bencK  = (const float*)d_in[4];
    const float* WencP1 = (const float*)d_in[5];
    const float* bencP1 = (const float*)d_in[6];
    const float* WencP2 = (const float*)d_in[7];
    const float* bencP2 = (const float*)d_in[8];
    const float* WK1 = (const float*)d_in[9];
    const float* bK1 = (const float*)d_in[10];
    const float* WK2 = (const float*)d_in[11];
    const float* bK2 = (const float*)d_in[12];
    const float* WK3 = (const float*)d_in[13];
    const float* bK3 = (const float*)d_in[14];
    const float* WU1 = (const float*)d_in[15];
    const float* bU1 = (const float*)d_in[16];
    const float* WU2 = (const float*)d_in[17];
    const float* bU2 = (const float*)d_in[18];
    const float* WU3 = (const float*)d_in[19];
    const float* bU3 = (const float*)d_in[20];
    const float* WH  = (const float*)d_in[21];
    const float* bH  = (const float*)d_in[22];
    const float* WD  = (const float*)d_in[23];
    const float* bD  = (const float*)d_in[24];

    int n = in_sizes[0] / 64;
    int e = in_sizes[1];
    if (n > MAXN) n = MAXN;

    cudaFuncSetAttribute(edge_mlp, cudaFuncAttributeMaxDynamicSharedMemorySize,
                         EDGE_SMEM);

    void *pS, *pdeg, *pEnew;
    cudaGetSymbolAddress(&pS,    g_S);
    cudaGetSymbolAddress(&pdeg,  g_deg);
    cudaGetSymbolAddress(&pEnew, g_Enew);
    cudaMemsetAsync(pS,    0, (size_t)n * 64 * sizeof(float));
    cudaMemsetAsync(pdeg,  0, (size_t)n * sizeof(float));
    cudaMemsetAsync(pEnew, 0, (size_t)n * 64 * sizeof(float));

    int nb = (n + 127) / 128;
    node_pre<<<nb, 128>>>(x, WencP1, bencP1, WencP2, bencP2, n);
    edge_scatter<<<((size_t)e * 16 + 255) / 256, 256>>>(x, src, dst, e);
    node_mid<<<nb, 128>>>(WencK, bencK, WK1, bK1, WK2, bK2, WK3, bK3, n);
    edge_mlp<<<444, 128, EDGE_SMEM>>>(src, dst, WU1, bU1, WU2, bU2, WU3, bU3, e);
    node_post<<<nb, 128>>>(WH, bH, WD, bD, (float*)d_out, n);
}

// round 6
// speedup vs baseline: 2.2379x; 1.1806x over previous
#include <cuda_runtime.h>

typedef unsigned long long ull;

#define MAXN 50000

// ---------------- device scratch (no allocations allowed) ----------------
__device__ float g_S   [MAXN * 64];
__device__ float g_deg [MAXN];
__device__ float g_h1  [MAXN * 32];
__device__ float g_h2  [MAXN * 32];
__device__ float g_En  [MAXN * 64];
__device__ float g_Enew[MAXN * 64];

// ---------------- helpers ----------------
__device__ __forceinline__ void fma4(float4& acc, float s, const float4& wv) {
    acc.x += s * wv.x; acc.y += s * wv.y; acc.z += s * wv.z; acc.w += s * wv.w;
}
__device__ __forceinline__ ull pack2(float a, float b) {
    ull r; asm("mov.b64 %0, {%1, %2};" : "=l"(r) : "f"(a), "f"(b)); return r;
}
__device__ __forceinline__ void unpack2(ull v, float& a, float& b) {
    asm("mov.b64 {%0, %1}, %2;" : "=f"(a), "=f"(b) : "l"(v));
}
__device__ __forceinline__ ull ffma2(ull a, ull b, ull c) {
    ull d; asm("fma.rn.f32x2 %0, %1, %2, %3;" : "=l"(d) : "l"(a), "l"(b), "l"(c));
    return d;
}
__device__ __forceinline__ float tanh_fast(float x) {
    float y; asm("tanh.approx.f32 %0, %1;" : "=f"(y) : "f"(x)); return y;
}

// ---------------- kernel 1: per-node h1/h2 = q @ WencP{1,2} + b ----------
__global__ __launch_bounds__(128) void node_pre(
    const float* __restrict__ x,
    const float* __restrict__ W1, const float* __restrict__ b1,
    const float* __restrict__ W2, const float* __restrict__ b2, int n)
{
    __shared__ float4 sW1[32 * 8], sW2[32 * 8], sb1[8], sb2[8];
    for (int i = threadIdx.x; i < 32 * 8; i += 128) {
        sW1[i] = ((const float4*)W1)[i];
        sW2[i] = ((const float4*)W2)[i];
    }
    if (threadIdx.x < 8) {
        sb1[threadIdx.x] = ((const float4*)b1)[threadIdx.x];
        sb2[threadIdx.x] = ((const float4*)b2)[threadIdx.x];
    }
    __syncthreads();
    int i = blockIdx.x * 128 + threadIdx.x;
    if (i >= n) return;

    float q[32];
    const float4* xp = (const float4*)(x + (size_t)i * 64);
#pragma unroll
    for (int k4 = 0; k4 < 8; k4++) {
        float4 v = xp[k4];
        q[4*k4] = v.x; q[4*k4+1] = v.y; q[4*k4+2] = v.z; q[4*k4+3] = v.w;
    }
    float4* o1 = (float4*)(g_h1 + (size_t)i * 32);
    float4* o2 = (float4*)(g_h2 + (size_t)i * 32);
#pragma unroll
    for (int jb = 0; jb < 8; jb++) {
        float4 a1 = sb1[jb], a2 = sb2[jb];
#pragma unroll
        for (int k = 0; k < 32; k++) {
            fma4(a1, q[k], sW1[k*8 + jb]);
            fma4(a2, q[k], sW2[k*8 + jb]);
        }
        o1[jb] = a1;
        o2[jb] = a2;
    }
}

// ---------------- kernel 2: S = segment_sum(x[src], dst), deg ------------
__global__ void edge_scatter(const float* __restrict__ x,
                             const int* __restrict__ src,
                             const int* __restrict__ dst, int e_total)
{
    int t = blockIdx.x * blockDim.x + threadIdx.x;
    int e = t >> 4;
    if (e >= e_total) return;
    int j4 = t & 15;
    int s = __ldg(src + e);
    int d = __ldg(dst + e);
    float4 v = __ldg((const float4*)(x + (size_t)s * 64) + j4);
    float* o = g_S + (size_t)d * 64 + j4 * 4;
    atomicAdd(o + 0, v.x);
    atomicAdd(o + 1, v.y);
    atomicAdd(o + 2, v.z);
    atomicAdd(o + 3, v.w);
    if (j4 == 0) atomicAdd(&g_deg[d], 1.0f);
}

// ------ kernel 3: hK_agg = S[:,32:]@WencK + deg*b ; E_node = mlp3 --------
__global__ __launch_bounds__(128) void node_mid(
    const float* __restrict__ WencK, const float* __restrict__ bencK,
    const float* __restrict__ WK1, const float* __restrict__ bK1,
    const float* __restrict__ WK2, const float* __restrict__ bK2,
    const float* __restrict__ WK3, const float* __restrict__ bK3, int n)
{
    __shared__ float4 sWe[32 * 8],  sbe[8];
    __shared__ float4 sW1[32 * 16], sb1[16];
    __shared__ float4 sW2[64 * 16], sb2[16];
    __shared__ float4 sW3[64 * 16], sb3[16];
    for (int i = threadIdx.x; i < 32 * 8;  i += 128) sWe[i] = ((const float4*)WencK)[i];
    for (int i = threadIdx.x; i < 32 * 16; i += 128) sW1[i] = ((const float4*)WK1)[i];
    for (int i = threadIdx.x; i < 64 * 16; i += 128) sW2[i] = ((const float4*)WK2)[i];
    for (int i = threadIdx.x; i < 64 * 16; i += 128) sW3[i] = ((const float4*)WK3)[i];
    if (threadIdx.x < 8)  sbe[threadIdx.x] = ((const float4*)bencK)[threadIdx.x];
    if (threadIdx.x < 16) {
        sb1[threadIdx.x] = ((const float4*)bK1)[threadIdx.x];
        sb2[threadIdx.x] = ((const float4*)bK2)[threadIdx.x];
        sb3[threadIdx.x] = ((const float4*)bK3)[threadIdx.x];
    }
    __syncthreads();
    int i = blockIdx.x * 128 + threadIdx.x;
    if (i >= n) return;

    float p[32];
    const float4* Sp = (const float4*)(g_S + (size_t)i * 64);
#pragma unroll
    for (int k4 = 0; k4 < 8; k4++) {
        float4 v = Sp[8 + k4];
        p[4*k4] = v.x; p[4*k4+1] = v.y; p[4*k4+2] = v.z; p[4*k4+3] = v.w;
    }
    float dg = g_deg[i];

    float hK[32];
#pragma unroll
    for (int jb = 0; jb < 8; jb++) {
        float4 b = sbe[jb];
        float4 acc = make_float4(dg*b.x, dg*b.y, dg*b.z, dg*b.w);
#pragma unroll
        for (int k = 0; k < 32; k++) fma4(acc, p[k], sWe[k*8 + jb]);
        hK[4*jb] = acc.x; hK[4*jb+1] = acc.y; hK[4*jb+2] = acc.z; hK[4*jb+3] = acc.w;
    }

    float t1[64];
#pragma unroll
    for (int jb = 0; jb < 16; jb++) {
        float4 acc = sb1[jb];
#pragma unroll
        for (int k = 0; k < 32; k++) fma4(acc, hK[k], sW1[k*16 + jb]);
        t1[4*jb]   = tanh_fast(acc.x); t1[4*jb+1] = tanh_fast(acc.y);
        t1[4*jb+2] = tanh_fast(acc.z); t1[4*jb+3] = tanh_fast(acc.w);
    }

    float t2[64];
#pragma unroll
    for (int jb = 0; jb < 16; jb++) {
        float4 acc = sb2[jb];
#pragma unroll
        for (int k = 0; k < 64; k++) fma4(acc, t1[k], sW2[k*16 + jb]);
        t2[4*jb]   = fmaxf(acc.x, 0.f); t2[4*jb+1] = fmaxf(acc.y, 0.f);
        t2[4*jb+2] = fmaxf(acc.z, 0.f); t2[4*jb+3] = fmaxf(acc.w, 0.f);
    }

    float4* Eo = (float4*)(g_En + (size_t)i * 64);
#pragma unroll
    for (int jb = 0; jb < 16; jb++) {
        float4 acc = sb3[jb];
#pragma unroll
        for (int k = 0; k < 64; k++) fma4(acc, t2[k], sW3[k*16 + jb]);
        Eo[jb] = acc;
    }
}

// ======================= kernel 4: tiled edge MLP =========================
// 256 threads, tile = 128 edges. Thread grid 16 (edge groups) x 16 (col
// groups); each thread: 8 edges x 4 cols = 16 f32x2 accs over EDGE pairs.
// A in smem NON-duplicated: sA[k][e] (row = 128 floats + 4 pad). Per k a
// thread loads its 8 edges as 2 LDS.128 (warp-broadcast), and one float4 of
// W, duplicated into (w,w) pairs in registers (alu pipe, which is idle).
// ROWA*4 % 16 == 0 (16B rows) and 4*ROWA % 32 == 16 (degree-2 store banks).
static constexpr int TILE_E = 128;
static constexpr int ROWA = 132;
// smem map (bytes)
static constexpr int OFF_W1 = 0;         // 32x64 f32 =  8192
static constexpr int OFF_W2 = 8192;      // 64x64 f32 = 16384
static constexpr int OFF_W3 = 24576;     // 64x64 f32 = 16384
static constexpr int OFF_B1 = 40960;     // 64 ull dup = 512
static constexpr int OFF_B2 = 41472;
static constexpr int OFF_B3 = 41984;
static constexpr int OFF_SRC = 42496;    // 128 int
static constexpr int OFF_DST = 43008;    // 128 int
static constexpr int OFF_A  = 43520;     // 64 x 132 f32 = 33792
static constexpr int EDGE_SMEM = OFF_A + 64 * ROWA * 4;   // 77312

template<int K>
__device__ __forceinline__ void gemm_pair(ull acc[16], const float* sA,
                                          const float* sW, const ull* sbd,
                                          int e0, int c0)
{
#pragma unroll
    for (int p = 0; p < 4; p++) {
        acc[p*4+0] = sbd[c0+0]; acc[p*4+1] = sbd[c0+1];
        acc[p*4+2] = sbd[c0+2]; acc[p*4+3] = sbd[c0+3];
    }
#pragma unroll 8
    for (int k = 0; k < K; k++) {
        const ulonglong2* ap = (const ulonglong2*)&sA[k*ROWA + e0];
        ulonglong2 A01 = ap[0];   // edge pairs 0,1
        ulonglong2 A23 = ap[1];   // edge pairs 2,3
        float4 w = *(const float4*)&sW[k*64 + c0];
        ull b0 = pack2(w.x, w.x), b1 = pack2(w.y, w.y);
        ull b2 = pack2(w.z, w.z), b3 = pack2(w.w, w.w);
        acc[0]  = ffma2(A01.x, b0, acc[0]);  acc[1]  = ffma2(A01.x, b1, acc[1]);
        acc[2]  = ffma2(A01.x, b2, acc[2]);  acc[3]  = ffma2(A01.x, b3, acc[3]);
        acc[4]  = ffma2(A01.y, b0, acc[4]);  acc[5]  = ffma2(A01.y, b1, acc[5]);
        acc[6]  = ffma2(A01.y, b2, acc[6]);  acc[7]  = ffma2(A01.y, b3, acc[7]);
        acc[8]  = ffma2(A23.x, b0, acc[8]);  acc[9]  = ffma2(A23.x, b1, acc[9]);
        acc[10] = ffma2(A23.x, b2, acc[10]); acc[11] = ffma2(A23.x, b3, acc[11]);
        acc[12] = ffma2(A23.y, b0, acc[12]); acc[13] = ffma2(A23.y, b1, acc[13]);
        acc[14] = ffma2(A23.y, b2, acc[14]); acc[15] = ffma2(A23.y, b3, acc[15]);
    }
}

__global__ void __launch_bounds__(256, 2) edge_mlp(
    const int* __restrict__ src, const int* __restrict__ dst,
    const float* __restrict__ WU1, const float* __restrict__ bU1,
    const float* __restrict__ WU2, const float* __restrict__ bU2,
    const float* __restrict__ WU3, const float* __restrict__ bU3, int e_total)
{
    extern __shared__ char smem[];
    float* sW1 = (float*)(smem + OFF_W1);
    float* sW2 = (float*)(smem + OFF_W2);
    float* sW3 = (float*)(smem + OFF_W3);
    ull* sbd1 = (ull*)(smem + OFF_B1);
    ull* sbd2 = (ull*)(smem + OFF_B2);
    ull* sbd3 = (ull*)(smem + OFF_B3);
    int* sSrc = (int*)(smem + OFF_SRC);
    int* sDst = (int*)(smem + OFF_DST);
    float* sA  = (float*)(smem + OFF_A);

    int tid = threadIdx.x;
    for (int i = tid; i < 512;  i += 256) ((float4*)sW1)[i] = ((const float4*)WU1)[i];
    for (int i = tid; i < 1024; i += 256) ((float4*)sW2)[i] = ((const float4*)WU2)[i];
    for (int i = tid; i < 1024; i += 256) ((float4*)sW3)[i] = ((const float4*)WU3)[i];
    if (tid < 64) {
        float b1 = __ldg(bU1 + tid), b2 = __ldg(bU2 + tid), b3 = __ldg(bU3 + tid);
        sbd1[tid] = pack2(b1, b1);
        sbd2[tid] = pack2(b2, b2);
        sbd3[tid] = pack2(b3, b3);
    }
    __syncthreads();

    int tr = tid >> 4;          // 0..15 -> edges tr*8..tr*8+7
    int tc = tid & 15;          // 0..15 -> cols tc*4..tc*4+3
    int e0 = tr * 8;
    int c0 = tc * 4;
    int eh = tid & 127;         // gather: edge within tile
    int half = tid >> 7;        // gather: which 16 features

    int ntiles = (e_total + TILE_E - 1) / TILE_E;
    for (int t = blockIdx.x; t < ntiles; t += gridDim.x) {
        int base = t * TILE_E;

        // ---- gather: eo = h1[src] + h2[dst] -> sA[k][e] (non-dup) ----
        {
            int ge = base + eh;
            bool valid = ge < e_total;
            int s = 0, d = 0;
            if (valid) { s = __ldg(src + ge); d = __ldg(dst + ge); }
            if (half == 0) { sSrc[eh] = s; sDst[eh] = d; }
            const float4* h1p = (const float4*)(g_h1 + (size_t)s * 32) + half * 4;
            const float4* h2p = (const float4*)(g_h2 + (size_t)d * 32) + half * 4;
#pragma unroll
            for (int q = 0; q < 4; q++) {
                float4 a = __ldg(h1p + q), b = __ldg(h2p + q);
                int kb = half * 16 + q * 4;
                sA[(kb+0)*ROWA + eh] = valid ? a.x + b.x : 0.f;
                sA[(kb+1)*ROWA + eh] = valid ? a.y + b.y : 0.f;
                sA[(kb+2)*ROWA + eh] = valid ? a.z + b.z : 0.f;
                sA[(kb+3)*ROWA + eh] = valid ? a.w + b.w : 0.f;
            }
        }
        __syncthreads();

        ull acc[16];

        // ---- layer 1: [32]->[64], tanh ----
        gemm_pair<32>(acc, sA, sW1, sbd1, e0, c0);
        __syncthreads();
#pragma unroll
        for (int p = 0; p < 4; p++) {
#pragma unroll
            for (int c = 0; c < 4; c++) {
                float a, b; unpack2(acc[p*4+c], a, b);
                *(ull*)&sA[(c0+c)*ROWA + e0 + 2*p] =
                    pack2(tanh_fast(a), tanh_fast(b));
            }
        }
        __syncthreads();

        // ---- layer 2: [64]->[64], relu ----
        gemm_pair<64>(acc, sA, sW2, sbd2, e0, c0);
        __syncthreads();
#pragma unroll
        for (int p = 0; p < 4; p++) {
#pragma unroll
            for (int c = 0; c < 4; c++) {
                float a, b; unpack2(acc[p*4+c], a, b);
                *(ull*)&sA[(c0+c)*ROWA + e0 + 2*p] =
                    pack2(fmaxf(a, 0.f), fmaxf(b, 0.f));
            }
        }
        __syncthreads();

        // ---- layer 3: [64]->[64], * E_node[src], scatter to E_new[dst] ----
        gemm_pair<64>(acc, sA, sW3, sbd3, e0, c0);
#pragma unroll
        for (int p = 0; p < 4; p++) {
            float v0[4], v1[4];
#pragma unroll
            for (int c = 0; c < 4; c++) unpack2(acc[p*4+c], v0[c], v1[c]);
            int ee = e0 + 2*p;
#pragma unroll
            for (int which = 0; which < 2; which++) {
                int edge = ee + which;
                if (base + edge < e_total) {
                    int s = sSrc[edge], d = sDst[edge];
                    float4 En4 = __ldg((const float4*)(g_En + (size_t)s * 64 + c0));
                    float* Ew = g_Enew + (size_t)d * 64 + c0;
                    const float* v = which ? v1 : v0;
                    atomicAdd(Ew + 0, v[0] * En4.x);
                    atomicAdd(Ew + 1, v[1] * En4.y);
                    atomicAdd(Ew + 2, v[2] * En4.z);
                    atomicAdd(Ew + 3, v[3] * En4.w);
                }
            }
        }
        __syncthreads();   // protect sA/sSrc before next tile's gather
    }
}

// ------ kernel 5: dH = E_new@WH + bH ; d_agg = S@WD[:,32:] + deg*b ; out -
__global__ __launch_bounds__(128) void node_post(
    const float* __restrict__ WH, const float* __restrict__ bH,
    const float* __restrict__ WD, const float* __restrict__ bD,
    float* __restrict__ out, int n)
{
    __shared__ float4 sWH[64 * 16], sbH[16];
    __shared__ float4 sWD[64 * 8],  sbD[8];
    for (int i = threadIdx.x; i < 64 * 16; i += 128) sWH[i] = ((const float4*)WH)[i];
    for (int i = threadIdx.x; i < 64 * 8; i += 128) {
        int k = i >> 3, jb = i & 7;
        sWD[i] = ((const float4*)(WD + k * 64 + 32))[jb];
    }
    if (threadIdx.x < 16) sbH[threadIdx.x] = ((const float4*)bH)[threadIdx.x];
    if (threadIdx.x < 8)  sbD[threadIdx.x] = ((const float4*)(bD + 32))[threadIdx.x];
    __syncthreads();
    int i = blockIdx.x * 128 + threadIdx.x;
    if (i >= n) return;

    float En[64];
    const float4* Ep = (const float4*)(g_Enew + (size_t)i * 64);
#pragma unroll
    for (int k4 = 0; k4 < 16; k4++) {
        float4 v = Ep[k4];
        En[4*k4] = v.x; En[4*k4+1] = v.y; En[4*k4+2] = v.z; En[4*k4+3] = v.w;
    }

    float4* op = (float4*)(out + (size_t)i * 64);
    float dlo[32];
#pragma unroll
    for (int jb = 0; jb < 16; jb++) {
        float4 acc = sbH[jb];
#pragma unroll
        for (int k = 0; k < 64; k++) fma4(acc, En[k], sWH[k*16 + jb]);
        if (jb >= 8) {
            op[jb - 8] = acc;
        } else {
            dlo[4*jb] = acc.x; dlo[4*jb+1] = acc.y;
            dlo[4*jb+2] = acc.z; dlo[4*jb+3] = acc.w;
        }
    }

    float S[64];
    const float4* Sp = (const float4*)(g_S + (size_t)i * 64);
#pragma unroll
    for (int k4 = 0; k4 < 16; k4++) {
        float4 v = Sp[k4];
        S[4*k4] = v.x; S[4*k4+1] = v.y; S[4*k4+2] = v.z; S[4*k4+3] = v.w;
    }
    float dg = g_deg[i];
#pragma unroll
    for (int jb = 0; jb < 8; jb++) {
        float4 b = sbD[jb];
        float4 acc = make_float4(dg*b.x, dg*b.y, dg*b.z, dg*b.w);
#pragma unroll
        for (int k = 0; k < 64; k++) fma4(acc, S[k], sWD[k*8 + jb]);
        float4 o;
        o.x = -dlo[4*jb]   - acc.x;
        o.y = -dlo[4*jb+1] - acc.y;
        o.z = -dlo[4*jb+2] - acc.z;
        o.w = -dlo[4*jb+3] - acc.w;
        op[8 + jb] = o;
    }
}

// -------------------------------------------------------------------------
extern "C" void kernel_launch(void* const* d_in, const int* in_sizes, int n_in,
                              void* d_out, int out_size)
{
    const float* x      = (const float*)d_in[0];
    const int*   src    = (const int*)  d_in[1];
    const int*   dst    = (const int*)  d_in[2];
    const float* WencK  = (const float*)d_in[3];
    const float* bencK  = (const float*)d_in[4];
    const float* WencP1 = (const float*)d_in[5];
    const float* bencP1 = (const float*)d_in[6];
    const float* WencP2 = (const float*)d_in[7];
    const float* bencP2 = (const float*)d_in[8];
    const float* WK1 = (const float*)d_in[9];
    const float* bK1 = (const float*)d_in[10];
    const float* WK2 = (const float*)d_in[11];
    const float* bK2 = (const float*)d_in[12];
    const float* WK3 = (const float*)d_in[13];
    const float* bK3 = (const float*)d_in[14];
    const float* WU1 = (const float*)d_in[15];
    const float* bU1 = (const float*)d_in[16];
    const float* WU2 = (const float*)d_in[17];
    const float* bU2 = (const float*)d_in[18];
    const float* WU3 = (const float*)d_in[19];
    const float* bU3 = (const float*)d_in[20];
    const float* WH  = (const float*)d_in[21];
    const float* bH  = (const float*)d_in[22];
    const float* WD  = (const float*)d_in[23];
    const float* bD  = (const float*)d_in[24];

    int n = in_sizes[0] / 64;
    int e = in_sizes[1];
    if (n > MAXN) n = MAXN;

    cudaFuncSetAttribute(edge_mlp, cudaFuncAttributeMaxDynamicSharedMemorySize,
                         EDGE_SMEM);

    void *pS, *pdeg, *pEnew;
    cudaGetSymbolAddress(&pS,    g_S);
    cudaGetSymbolAddress(&pdeg,  g_deg);
    cudaGetSymbolAddress(&pEnew, g_Enew);
    cudaMemsetAsync(pS,    0, (size_t)n * 64 * sizeof(float));
    cudaMemsetAsync(pdeg,  0, (size_t)n * sizeof(float));
    cudaMemsetAsync(pEnew, 0, (size_t)n * 64 * sizeof(float));

    int nb = (n + 127) / 128;
    node_pre<<<nb, 128>>>(x, WencP1, bencP1, WencP2, bencP2, n);
    edge_scatter<<<((size_t)e * 16 + 255) / 256, 256>>>(x, src, dst, e);
    node_mid<<<nb, 128>>>(WencK, bencK, WK1, bK1, WK2, bK2, WK3, bK3, n);
    edge_mlp<<<444, 256, EDGE_SMEM>>>(src, dst, WU1, bU1, WU2, bU2, WU3, bU3, e);
    node_post<<<nb, 128>>>(WH, bH, WD, bD, (float*)d_out, n);
}

// round 7
// speedup vs baseline: 2.6036x; 1.1634x over previous
#include <cuda_runtime.h>

typedef unsigned long long ull;

#define MAXN 50000

// ---------------- device scratch (no allocations allowed) ----------------
__device__ float g_S   [MAXN * 64];
__device__ float g_deg [MAXN];
__device__ float g_h1  [MAXN * 32];
__device__ float g_h2  [MAXN * 32];
__device__ float g_En  [MAXN * 64];
__device__ float g_Enew[MAXN * 64];

// ---------------- helpers ----------------
__device__ __forceinline__ void fma4(float4& acc, float s, const float4& wv) {
    acc.x += s * wv.x; acc.y += s * wv.y; acc.z += s * wv.z; acc.w += s * wv.w;
}
__device__ __forceinline__ ull pack2(float a, float b) {
    ull r; asm("mov.b64 %0, {%1, %2};" : "=l"(r) : "f"(a), "f"(b)); return r;
}
__device__ __forceinline__ void unpack2(ull v, float& a, float& b) {
    asm("mov.b64 {%0, %1}, %2;" : "=f"(a), "=f"(b) : "l"(v));
}
__device__ __forceinline__ ull ffma2(ull a, ull b, ull c) {
    ull d; asm("fma.rn.f32x2 %0, %1, %2, %3;" : "=l"(d) : "l"(a), "l"(b), "l"(c));
    return d;
}
__device__ __forceinline__ float tanh_fast(float x) {
    float y; asm("tanh.approx.f32 %0, %1;" : "=f"(y) : "f"(x)); return y;
}

// ---------------- kernel 1: per-node h1/h2 = q @ WencP{1,2} + b ----------
__global__ __launch_bounds__(128) void node_pre(
    const float* __restrict__ x,
    const float* __restrict__ W1, const float* __restrict__ b1,
    const float* __restrict__ W2, const float* __restrict__ b2, int n)
{
    __shared__ float4 sW1[32 * 8], sW2[32 * 8], sb1[8], sb2[8];
    for (int i = threadIdx.x; i < 32 * 8; i += 128) {
        sW1[i] = ((const float4*)W1)[i];
        sW2[i] = ((const float4*)W2)[i];
    }
    if (threadIdx.x < 8) {
        sb1[threadIdx.x] = ((const float4*)b1)[threadIdx.x];
        sb2[threadIdx.x] = ((const float4*)b2)[threadIdx.x];
    }
    __syncthreads();
    int i = blockIdx.x * 128 + threadIdx.x;
    if (i >= n) return;

    float q[32];
    const float4* xp = (const float4*)(x + (size_t)i * 64);
#pragma unroll
    for (int k4 = 0; k4 < 8; k4++) {
        float4 v = xp[k4];
        q[4*k4] = v.x; q[4*k4+1] = v.y; q[4*k4+2] = v.z; q[4*k4+3] = v.w;
    }
    float4* o1 = (float4*)(g_h1 + (size_t)i * 32);
    float4* o2 = (float4*)(g_h2 + (size_t)i * 32);
#pragma unroll
    for (int jb = 0; jb < 8; jb++) {
        float4 a1 = sb1[jb], a2 = sb2[jb];
#pragma unroll
        for (int k = 0; k < 32; k++) {
            fma4(a1, q[k], sW1[k*8 + jb]);
            fma4(a2, q[k], sW2[k*8 + jb]);
        }
        o1[jb] = a1;
        o2[jb] = a2;
    }
}

// ---------------- kernel 2: S = segment_sum(x[src], dst), deg ------------
__global__ void edge_scatter(const float* __restrict__ x,
                             const int* __restrict__ src,
                             const int* __restrict__ dst, int e_total)
{
    int t = blockIdx.x * blockDim.x + threadIdx.x;
    int e = t >> 4;
    if (e >= e_total) return;
    int j4 = t & 15;
    int s = __ldg(src + e);
    int d = __ldg(dst + e);
    float4 v = __ldg((const float4*)(x + (size_t)s * 64) + j4);
    atomicAdd((float4*)(g_S + (size_t)d * 64 + j4 * 4), v);
    if (j4 == 0) atomicAdd(&g_deg[d], 1.0f);
}

// ------ kernel 3: hK_agg = S[:,32:]@WencK + deg*b ; E_node = mlp3 --------
__global__ __launch_bounds__(128) void node_mid(
    const float* __restrict__ WencK, const float* __restrict__ bencK,
    const float* __restrict__ WK1, const float* __restrict__ bK1,
    const float* __restrict__ WK2, const float* __restrict__ bK2,
    const float* __restrict__ WK3, const float* __restrict__ bK3, int n)
{
    __shared__ float4 sWe[32 * 8],  sbe[8];
    __shared__ float4 sW1[32 * 16], sb1[16];
    __shared__ float4 sW2[64 * 16], sb2[16];
    __shared__ float4 sW3[64 * 16], sb3[16];
    for (int i = threadIdx.x; i < 32 * 8;  i += 128) sWe[i] = ((const float4*)WencK)[i];
    for (int i = threadIdx.x; i < 32 * 16; i += 128) sW1[i] = ((const float4*)WK1)[i];
    for (int i = threadIdx.x; i < 64 * 16; i += 128) sW2[i] = ((const float4*)WK2)[i];
    for (int i = threadIdx.x; i < 64 * 16; i += 128) sW3[i] = ((const float4*)WK3)[i];
    if (threadIdx.x < 8)  sbe[threadIdx.x] = ((const float4*)bencK)[threadIdx.x];
    if (threadIdx.x < 16) {
        sb1[threadIdx.x] = ((const float4*)bK1)[threadIdx.x];
        sb2[threadIdx.x] = ((const float4*)bK2)[threadIdx.x];
        sb3[threadIdx.x] = ((const float4*)bK3)[threadIdx.x];
    }
    __syncthreads();
    int i = blockIdx.x * 128 + threadIdx.x;
    if (i >= n) return;

    float p[32];
    const float4* Sp = (const float4*)(g_S + (size_t)i * 64);
#pragma unroll
    for (int k4 = 0; k4 < 8; k4++) {
        float4 v = Sp[8 + k4];
        p[4*k4] = v.x; p[4*k4+1] = v.y; p[4*k4+2] = v.z; p[4*k4+3] = v.w;
    }
    float dg = g_deg[i];

    float hK[32];
#pragma unroll
    for (int jb = 0; jb < 8; jb++) {
        float4 b = sbe[jb];
        float4 acc = make_float4(dg*b.x, dg*b.y, dg*b.z, dg*b.w);
#pragma unroll
        for (int k = 0; k < 32; k++) fma4(acc, p[k], sWe[k*8 + jb]);
        hK[4*jb] = acc.x; hK[4*jb+1] = acc.y; hK[4*jb+2] = acc.z; hK[4*jb+3] = acc.w;
    }

    float t1[64];
#pragma unroll
    for (int jb = 0; jb < 16; jb++) {
        float4 acc = sb1[jb];
#pragma unroll
        for (int k = 0; k < 32; k++) fma4(acc, hK[k], sW1[k*16 + jb]);
        t1[4*jb]   = tanh_fast(acc.x); t1[4*jb+1] = tanh_fast(acc.y);
        t1[4*jb+2] = tanh_fast(acc.z); t1[4*jb+3] = tanh_fast(acc.w);
    }

    float t2[64];
#pragma unroll
    for (int jb = 0; jb < 16; jb++) {
        float4 acc = sb2[jb];
#pragma unroll
        for (int k = 0; k < 64; k++) fma4(acc, t1[k], sW2[k*16 + jb]);
        t2[4*jb]   = fmaxf(acc.x, 0.f); t2[4*jb+1] = fmaxf(acc.y, 0.f);
        t2[4*jb+2] = fmaxf(acc.z, 0.f); t2[4*jb+3] = fmaxf(acc.w, 0.f);
    }

    float4* Eo = (float4*)(g_En + (size_t)i * 64);
#pragma unroll
    for (int jb = 0; jb < 16; jb++) {
        float4 acc = sb3[jb];
#pragma unroll
        for (int k = 0; k < 64; k++) fma4(acc, t2[k], sW3[k*16 + jb]);
        Eo[jb] = acc;
    }
}

// ======================= kernel 4: tiled edge MLP =========================
// 256 threads, tile = 128 edges. Logical grid 16 tr x 16 tc; WARP-INTERNAL
// layout is 4 tr-groups x 8 tc-groups so that per k: W float4 load = 8
// distinct 16B (1 wavefront, conflict-free) and A = 2 LDS.128 with 4 distinct
// 16B each (1 wf each, bank-skewed). Edge index is SKEWED in smem by
// +4 floats per 32-edge group so tr groups (128B apart) land on distinct banks.
static constexpr int TILE_E = 128;
static constexpr int ROWA = 140;   // 128 data + 12 skew; 140*4 % 16 == 0
// smem map (bytes)
static constexpr int OFF_W1 = 0;         // 32x64 f32 =  8192
static constexpr int OFF_W2 = 8192;      // 64x64 f32 = 16384
static constexpr int OFF_W3 = 24576;     // 64x64 f32 = 16384
static constexpr int OFF_B1 = 40960;     // 64 ull dup = 512
static constexpr int OFF_B2 = 41472;
static constexpr int OFF_B3 = 41984;
static constexpr int OFF_SRC = 42496;    // 128 int
static constexpr int OFF_DST = 43008;    // 128 int
static constexpr int OFF_A  = 43520;     // 64 x 140 f32 = 35840
static constexpr int EDGE_SMEM = OFF_A + 64 * ROWA * 4;   // 79360

__device__ __forceinline__ int skew_e(int e) { return e + 4 * (e >> 5); }

template<int K>
__device__ __forceinline__ void gemm_pair(ull acc[16], const float* sA,
                                          const float* sW, const ull* sbd,
                                          int e0s, int c0)
{
#pragma unroll
    for (int p = 0; p < 4; p++) {
        acc[p*4+0] = sbd[c0+0]; acc[p*4+1] = sbd[c0+1];
        acc[p*4+2] = sbd[c0+2]; acc[p*4+3] = sbd[c0+3];
    }
#pragma unroll 8
    for (int k = 0; k < K; k++) {
        const ulonglong2* ap = (const ulonglong2*)&sA[k*ROWA + e0s];
        ulonglong2 A01 = ap[0];   // edge pairs 0,1
        ulonglong2 A23 = ap[1];   // edge pairs 2,3
        float4 w = *(const float4*)&sW[k*64 + c0];
        ull b0 = pack2(w.x, w.x), b1 = pack2(w.y, w.y);
        ull b2 = pack2(w.z, w.z), b3 = pack2(w.w, w.w);
        acc[0]  = ffma2(A01.x, b0, acc[0]);  acc[1]  = ffma2(A01.x, b1, acc[1]);
        acc[2]  = ffma2(A01.x, b2, acc[2]);  acc[3]  = ffma2(A01.x, b3, acc[3]);
        acc[4]  = ffma2(A01.y, b0, acc[4]);  acc[5]  = ffma2(A01.y, b1, acc[5]);
        acc[6]  = ffma2(A01.y, b2, acc[6]);  acc[7]  = ffma2(A01.y, b3, acc[7]);
        acc[8]  = ffma2(A23.x, b0, acc[8]);  acc[9]  = ffma2(A23.x, b1, acc[9]);
        acc[10] = ffma2(A23.x, b2, acc[10]); acc[11] = ffma2(A23.x, b3, acc[11]);
        acc[12] = ffma2(A23.y, b0, acc[12]); acc[13] = ffma2(A23.y, b1, acc[13]);
        acc[14] = ffma2(A23.y, b2, acc[14]); acc[15] = ffma2(A23.y, b3, acc[15]);
    }
}

__global__ void __launch_bounds__(256, 2) edge_mlp(
    const int* __restrict__ src, const int* __restrict__ dst,
    const float* __restrict__ WU1, const float* __restrict__ bU1,
    const float* __restrict__ WU2, const float* __restrict__ bU2,
    const float* __restrict__ WU3, const float* __restrict__ bU3, int e_total)
{
    extern __shared__ char smem[];
    float* sW1 = (float*)(smem + OFF_W1);
    float* sW2 = (float*)(smem + OFF_W2);
    float* sW3 = (float*)(smem + OFF_W3);
    ull* sbd1 = (ull*)(smem + OFF_B1);
    ull* sbd2 = (ull*)(smem + OFF_B2);
    ull* sbd3 = (ull*)(smem + OFF_B3);
    int* sSrc = (int*)(smem + OFF_SRC);
    int* sDst = (int*)(smem + OFF_DST);
    float* sA  = (float*)(smem + OFF_A);

    int tid = threadIdx.x;
    for (int i = tid; i < 512;  i += 256) ((float4*)sW1)[i] = ((const float4*)WU1)[i];
    for (int i = tid; i < 1024; i += 256) ((float4*)sW2)[i] = ((const float4*)WU2)[i];
    for (int i = tid; i < 1024; i += 256) ((float4*)sW3)[i] = ((const float4*)WU3)[i];
    if (tid < 64) {
        float b1 = __ldg(bU1 + tid), b2 = __ldg(bU2 + tid), b3 = __ldg(bU3 + tid);
        sbd1[tid] = pack2(b1, b1);
        sbd2[tid] = pack2(b2, b2);
        sbd3[tid] = pack2(b3, b3);
    }
    __syncthreads();

    // warp-internal layout: 4 tr-groups x 8 tc-groups
    int lane = tid & 31, w = tid >> 5;
    int tr = (lane >> 3) | ((w >> 1) << 2);   // 0..15
    int tc = (lane & 7)  | ((w & 1) << 3);    // 0..15
    int e0 = tr * 8;            // logical edge base
    int e0s = skew_e(e0);       // skewed smem base (16B aligned: e0%32 -> mult of 4)
    int c0 = tc * 4;
    int eh = tid & 127;         // gather: edge within tile
    int half = tid >> 7;        // gather: which 16 features

    int ntiles = (e_total + TILE_E - 1) / TILE_E;
    for (int t = blockIdx.x; t < ntiles; t += gridDim.x) {
        int base = t * TILE_E;

        // ---- gather: eo = h1[src] + h2[dst] -> sA[k][skew(e)] ----
        {
            int ge = base + eh;
            bool valid = ge < e_total;
            int s = 0, d = 0;
            if (valid) { s = __ldg(src + ge); d = __ldg(dst + ge); }
            if (half == 0) { sSrc[eh] = s; sDst[eh] = d; }
            int ehs = skew_e(eh);
            const float4* h1p = (const float4*)(g_h1 + (size_t)s * 32) + half * 4;
            const float4* h2p = (const float4*)(g_h2 + (size_t)d * 32) + half * 4;
#pragma unroll
            for (int q = 0; q < 4; q++) {
                float4 a = __ldg(h1p + q), b = __ldg(h2p + q);
                int kb = half * 16 + q * 4;
                sA[(kb+0)*ROWA + ehs] = valid ? a.x + b.x : 0.f;
                sA[(kb+1)*ROWA + ehs] = valid ? a.y + b.y : 0.f;
                sA[(kb+2)*ROWA + ehs] = valid ? a.z + b.z : 0.f;
                sA[(kb+3)*ROWA + ehs] = valid ? a.w + b.w : 0.f;
            }
        }
        __syncthreads();

        ull acc[16];

        // ---- layer 1: [32]->[64], tanh ----
        gemm_pair<32>(acc, sA, sW1, sbd1, e0s, c0);
        __syncthreads();
#pragma unroll
        for (int p = 0; p < 4; p++) {
#pragma unroll
            for (int c = 0; c < 4; c++) {
                float a, b; unpack2(acc[p*4+c], a, b);
                *(ull*)&sA[(c0+c)*ROWA + e0s + 2*p] =
                    pack2(tanh_fast(a), tanh_fast(b));
            }
        }
        __syncthreads();

        // ---- layer 2: [64]->[64], relu ----
        gemm_pair<64>(acc, sA, sW2, sbd2, e0s, c0);
        __syncthreads();
#pragma unroll
        for (int p = 0; p < 4; p++) {
#pragma unroll
            for (int c = 0; c < 4; c++) {
                float a, b; unpack2(acc[p*4+c], a, b);
                *(ull*)&sA[(c0+c)*ROWA + e0s + 2*p] =
                    pack2(fmaxf(a, 0.f), fmaxf(b, 0.f));
            }
        }
        __syncthreads();

        // ---- layer 3: [64]->[64], * E_node[src], scatter to E_new[dst] ----
        gemm_pair<64>(acc, sA, sW3, sbd3, e0s, c0);
#pragma unroll
        for (int p = 0; p < 4; p++) {
            float v0[4], v1[4];
#pragma unroll
            for (int c = 0; c < 4; c++) unpack2(acc[p*4+c], v0[c], v1[c]);
            int ee = e0 + 2*p;
#pragma unroll
            for (int which = 0; which < 2; which++) {
                int edge = ee + which;
                if (base + edge < e_total) {
                    int s = sSrc[edge], d = sDst[edge];
                    float4 En4 = __ldg((const float4*)(g_En + (size_t)s * 64 + c0));
                    const float* v = which ? v1 : v0;
                    float4 val = make_float4(v[0]*En4.x, v[1]*En4.y,
                                             v[2]*En4.z, v[3]*En4.w);
                    atomicAdd((float4*)(g_Enew + (size_t)d * 64 + c0), val);
                }
            }
        }
        __syncthreads();   // protect sA/sSrc before next tile's gather
    }
}

// ------ kernel 5: dH = E_new@WH + bH ; d_agg = S@WD[:,32:] + deg*b ; out -
__global__ __launch_bounds__(128) void node_post(
    const float* __restrict__ WH, const float* __restrict__ bH,
    const float* __restrict__ WD, const float* __restrict__ bD,
    float* __restrict__ out, int n)
{
    __shared__ float4 sWH[64 * 16], sbH[16];
    __shared__ float4 sWD[64 * 8],  sbD[8];
    for (int i = threadIdx.x; i < 64 * 16; i += 128) sWH[i] = ((const float4*)WH)[i];
    for (int i = threadIdx.x; i < 64 * 8; i += 128) {
        int k = i >> 3, jb = i & 7;
        sWD[i] = ((const float4*)(WD + k * 64 + 32))[jb];
    }
    if (threadIdx.x < 16) sbH[threadIdx.x] = ((const float4*)bH)[threadIdx.x];
    if (threadIdx.x < 8)  sbD[threadIdx.x] = ((const float4*)(bD + 32))[threadIdx.x];
    __syncthreads();
    int i = blockIdx.x * 128 + threadIdx.x;
    if (i >= n) return;

    float En[64];
    const float4* Ep = (const float4*)(g_Enew + (size_t)i * 64);
#pragma unroll
    for (int k4 = 0; k4 < 16; k4++) {
        float4 v = Ep[k4];
        En[4*k4] = v.x; En[4*k4+1] = v.y; En[4*k4+2] = v.z; En[4*k4+3] = v.w;
    }

    float4* op = (float4*)(out + (size_t)i * 64);
    float dlo[32];
#pragma unroll
    for (int jb = 0; jb < 16; jb++) {
        float4 acc = sbH[jb];
#pragma unroll
        for (int k = 0; k < 64; k++) fma4(acc, En[k], sWH[k*16 + jb]);
        if (jb >= 8) {
            op[jb - 8] = acc;
        } else {
            dlo[4*jb] = acc.x; dlo[4*jb+1] = acc.y;
            dlo[4*jb+2] = acc.z; dlo[4*jb+3] = acc.w;
        }
    }

    float S[64];
    const float4* Sp = (const float4*)(g_S + (size_t)i * 64);
#pragma unroll
    for (int k4 = 0; k4 < 16; k4++) {
        float4 v = Sp[k4];
        S[4*k4] = v.x; S[4*k4+1] = v.y; S[4*k4+2] = v.z; S[4*k4+3] = v.w;
    }
    float dg = g_deg[i];
#pragma unroll
    for (int jb = 0; jb < 8; jb++) {
        float4 b = sbD[jb];
        float4 acc = make_float4(dg*b.x, dg*b.y, dg*b.z, dg*b.w);
#pragma unroll
        for (int k = 0; k < 64; k++) fma4(acc, S[k], sWD[k*8 + jb]);
        float4 o;
        o.x = -dlo[4*jb]   - acc.x;
        o.y = -dlo[4*jb+1] - acc.y;
        o.z = -dlo[4*jb+2] - acc.z;
        o.w = -dlo[4*jb+3] - acc.w;
        op[8 + jb] = o;
    }
}

// -------------------------------------------------------------------------
extern "C" void kernel_launch(void* const* d_in, const int* in_sizes, int n_in,
                              void* d_out, int out_size)
{
    const float* x      = (const float*)d_in[0];
    const int*   src    = (const int*)  d_in[1];
    const int*   dst    = (const int*)  d_in[2];
    const float* WencK  = (const float*)d_in[3];
    const float* bencK  = (const float*)d_in[4];
    const float* WencP1 = (const float*)d_in[5];
    const float* bencP1 = (const float*)d_in[6];
    const float* WencP2 = (const float*)d_in[7];
    const float* bencP2 = (const float*)d_in[8];
    const float* WK1 = (const float*)d_in[9];
    const float* bK1 = (const float*)d_in[10];
    const float* WK2 = (const float*)d_in[11];
    const float* bK2 = (const float*)d_in[12];
    const float* WK3 = (const float*)d_in[13];
    const float* bK3 = (const float*)d_in[14];
    const float* WU1 = (const float*)d_in[15];
    const float* bU1 = (const float*)d_in[16];
    const float* WU2 = (const float*)d_in[17];
    const float* bU2 = (const float*)d_in[18];
    const float* WU3 = (const float*)d_in[19];
    const float* bU3 = (const float*)d_in[20];
    const float* WH  = (const float*)d_in[21];
    const float* bH  = (const float*)d_in[22];
    const float* WD  = (const float*)d_in[23];
    const float* bD  = (const float*)d_in[24];

    int n = in_sizes[0] / 64;
    int e = in_sizes[1];
    if (n > MAXN) n = MAXN;

    cudaFuncSetAttribute(edge_mlp, cudaFuncAttributeMaxDynamicSharedMemorySize,
                         EDGE_SMEM);

    void *pS, *pdeg, *pEnew;
    cudaGetSymbolAddress(&pS,    g_S);
    cudaGetSymbolAddress(&pdeg,  g_deg);
    cudaGetSymbolAddress(&pEnew, g_Enew);
    cudaMemsetAsync(pS,    0, (size_t)n * 64 * sizeof(float));
    cudaMemsetAsync(pdeg,  0, (size_t)n * sizeof(float));
    cudaMemsetAsync(pEnew, 0, (size_t)n * 64 * sizeof(float));

    int nb = (n + 127) / 128;
    node_pre<<<nb, 128>>>(x, WencP1, bencP1, WencP2, bencP2, n);
    edge_scatter<<<((size_t)e * 16 + 255) / 256, 256>>>(x, src, dst, e);
    node_mid<<<nb, 128>>>(WencK, bencK, WK1, bK1, WK2, bK2, WK3, bK3, n);
    edge_mlp<<<296, 256, EDGE_SMEM>>>(src, dst, WU1, bU1, WU2, bU2, WU3, bU3, e);
    node_post<<<nb, 128>>>(WH, bH, WD, bD, (float*)d_out, n);
}